// round 14
// baseline (speedup 1.0000x reference)
#include <cuda_runtime.h>
#include <math.h>
#include <stdint.h>

#define BATCH    8
#define CH       128
#define T_AUDIO  16384
#define COND_CH  80
#define T_MEL    32
#define N_LAYERS 4
#define KPL      (CH*CH*3)        /* 49152 */
#define KC       (KPL*N_LAYERS)   /* 196608 */
#define BC       (CH*N_LAYERS)    /* 512 */

#define NT       128              /* output chunk */
#define TILES    (T_AUDIO/NT)     /* 128 */
#define NCTAS    148              /* flattened persistent grid */
#define WHW      12288            /* words per W half (48KB): ks 0..11 */
#define WFULL    (2*WHW)          /* per (b,l) */
#define BUFW     160              /* compute grid width (chunk + 2*16 halo) */
#define XBW      184              /* xbf stride: 184%32==24 -> B frags conflict-free */

// ---------------- device scratch ----------------
__device__ float    g_h0[BATCH*64*T_MEL];
__device__ float    g_hmean[BATCH*64];
__device__ uint32_t g_Wh[BATCH*N_LAYERS*WFULL];
__device__ float    g_bias[BATCH*N_LAYERS*CH];

__device__ __forceinline__ float gelu_exact(float x) {
    return 0.5f * x * (1.0f + erff(x * 0.7071067811865475f));
}
__device__ __forceinline__ uint32_t pack_bf16x2(float lo, float hi) {
    uint32_t u;
    asm("cvt.rn.bf16x2.f32 %0, %1, %2;" : "=r"(u) : "f"(hi), "f"(lo));
    return u;
}
__device__ __forceinline__ uint32_t smem_u32(const void* p) {
    uint32_t a;
    asm("{ .reg .u64 t; cvta.to.shared.u64 t, %1; cvt.u32.u64 %0, t; }" : "=r"(a) : "l"(p));
    return a;
}
__device__ __forceinline__ void cp16(uint32_t dst, const void* src) {
    asm volatile("cp.async.cg.shared.global [%0], [%1], 16;" :: "r"(dst), "l"(src));
}
#define CP_COMMIT() asm volatile("cp.async.commit_group;" ::: "memory")
#define CP_WAIT1()  asm volatile("cp.async.wait_group 1;" ::: "memory")

#define MMA16(d_, a_, b_) \
  asm volatile("mma.sync.aligned.m16n8k16.row.col.f32.bf16.bf16.f32 " \
    "{%0,%1,%2,%3}, {%4,%5,%6,%7}, {%8,%9}, {%0,%1,%2,%3};" \
    : "+f"((d_)[0]), "+f"((d_)[1]), "+f"((d_)[2]), "+f"((d_)[3]) \
    : "r"((a_)[0]), "r"((a_)[1]), "r"((a_)[2]), "r"((a_)[3]), \
      "r"((b_)[0]), "r"((b_)[1]))

// =========================================================================
// Condnet C1: layer 0 (conv5, pad2, gelu). Grid (8 g, 8 b), 256 threads.
// =========================================================================
__global__ void __launch_bounds__(256)
cond_l0_kernel(const float* __restrict__ cond,
               const float* __restrict__ w0, const float* __restrict__ b0) {
    __shared__ float scp[COND_CH*36];     // padded: col = t+2
    __shared__ float sw[8*400];           // [ch][i*5+k] linear

    const int g = blockIdx.x;
    const int b = blockIdx.y;
    const int tid = threadIdx.x;
    const int wid = tid >> 5;
    const int lane = tid & 31;

    for (int idx = tid; idx < COND_CH*36; idx += 256) {
        const int row = idx / 36;
        const int t   = (idx - row*36) - 2;
        scp[idx] = (t >= 0 && t < T_MEL) ? cond[(b*COND_CH + row)*T_MEL + t] : 0.0f;
    }
    for (int idx = tid; idx < 8*400; idx += 256)
        sw[idx] = w0[g*8*400 + idx];
    __syncthreads();

    const float* wr = sw + wid*400;
    float acc = b0[g*8 + wid];
    #pragma unroll 4
    for (int i = 0; i < COND_CH; ++i) {
        const float4 w4 = *(const float4*)&wr[i*5];
        const float  w5 = wr[i*5 + 4];
        const float* xr = scp + i*36 + lane;
        acc += w4.x*xr[0] + w4.y*xr[1] + w4.z*xr[2] + w4.w*xr[3] + w5*xr[4];
    }
    g_h0[(b*64 + g*8 + wid)*T_MEL + lane] = gelu_exact(acc);
}

// =========================================================================
// Condnet C2: layer 1 (conv3, pad1, gelu) + mean over t. Grid 8, 1024 thr.
// =========================================================================
__global__ void __launch_bounds__(1024)
cond_l1_kernel(const float* __restrict__ w1, const float* __restrict__ b1) {
    extern __shared__ float smemf[];
    float* shp = smemf;             // [64][34] padded: col = t+1
    float* sw1 = smemf + 64*34;     // [64][192] linear

    const int b = blockIdx.x;
    const int tid = threadIdx.x;
    const int wid = tid >> 5;
    const int lane = tid & 31;

    for (int idx = tid; idx < 64*34; idx += 1024) {
        const int row = idx / 34;
        const int t   = (idx - row*34) - 1;
        shp[idx] = (t >= 0 && t < T_MEL) ? g_h0[(b*64 + row)*T_MEL + t] : 0.0f;
    }
    for (int idx = tid; idx < 64*192; idx += 1024)
        sw1[idx] = w1[idx];
    __syncthreads();

    const int o0 = wid*2, o1 = wid*2 + 1;
    const float* wr0 = sw1 + o0*192;
    const float* wr1 = sw1 + o1*192;
    float a0 = b1[o0], a1 = b1[o1];
    #pragma unroll 4
    for (int i = 0; i < 64; ++i) {
        const float* xr = shp + i*34 + lane;
        const float x0 = xr[0], x1 = xr[1], x2 = xr[2];
        const float2 wa = *(const float2*)&wr0[i*3];
        const float  wb = wr0[i*3 + 2];
        const float2 wc = *(const float2*)&wr1[i*3];
        const float  wd = wr1[i*3 + 2];
        a0 += wa.x*x0 + wa.y*x1 + wb*x2;
        a1 += wc.x*x0 + wc.y*x1 + wd*x2;
    }
    float v0 = gelu_exact(a0);
    float v1 = gelu_exact(a1);
    #pragma unroll
    for (int off = 16; off; off >>= 1) {
        v0 += __shfl_xor_sync(0xffffffffu, v0, off);
        v1 += __shfl_xor_sync(0xffffffffu, v1, off);
    }
    if (lane == 0) {
        g_hmean[b*64 + o0] = v0 * (1.0f/T_MEL);
        g_hmean[b*64 + o1] = v1 * (1.0f/T_MEL);
    }
}

// =========================================================================
// Kernel B: LVC weights -> bf16x2 fragment-major (unchanged)
// =========================================================================
__global__ void weights_kernel(const float* __restrict__ w2,
                               const float* __restrict__ b2) {
    __shared__ float sh[BATCH*64];
    const int tid = threadIdx.x;
    for (int i = tid; i < BATCH*64; i += 256) sh[i] = g_hmean[i];
    __syncthreads();

    if (blockIdx.x < 384) {
        const int gidx = blockIdx.x*256 + tid;     // < 98304
        const int l    = gidx / WFULL;
        const int e3   = gidx - l*WFULL;
        const int j    = e3 & 3;
        const int lane = (e3 >> 2) & 31;
        const int cb   = (e3 >> 7) & 7;
        const int ks   = e3 >> 10;
        const int co   = cb*16 + (lane >> 2) + (j & 1)*8;
        const int kl0  = (lane & 3)*2 + ((j >> 1) & 1)*8;
        const int kg0  = ks*16 + kl0;
        const int kk   = kg0 >> 7;
        const int ci0  = kg0 & 127;
        const size_t r0 = (size_t)l*KPL + (size_t)co*384 + ci0*3 + kk;
        const size_t r1 = r0 + 3;

        float a0[BATCH], a1[BATCH];
        #pragma unroll
        for (int b = 0; b < BATCH; ++b) { a0[b] = 0.0f; a1[b] = 0.0f; }
        const float4* wr0 = (const float4*)(w2 + r0*64);
        const float4* wr1 = (const float4*)(w2 + r1*64);
        #pragma unroll 4
        for (int q = 0; q < 16; ++q) {
            float4 u = wr0[q], v = wr1[q];
            #pragma unroll
            for (int b = 0; b < BATCH; ++b) {
                const float* h = sh + b*64 + q*4;
                a0[b] += u.x*h[0] + u.y*h[1] + u.z*h[2] + u.w*h[3];
                a1[b] += v.x*h[0] + v.y*h[1] + v.z*h[2] + v.w*h[3];
            }
        }
        const float bi0 = b2[r0], bi1 = b2[r1];
        #pragma unroll
        for (int b = 0; b < BATCH; ++b)
            g_Wh[(size_t)(b*N_LAYERS + l)*WFULL + e3] =
                pack_bf16x2(a0[b] + bi0, a1[b] + bi1);
    } else {
        const int idx = (blockIdx.x - 384)*256 + tid;   // < 512
        const size_t c = (size_t)KC + idx;
        float acc[BATCH];
        #pragma unroll
        for (int b = 0; b < BATCH; ++b) acc[b] = 0.0f;
        const float4* wr = (const float4*)(w2 + c*64);
        #pragma unroll 4
        for (int q = 0; q < 16; ++q) {
            float4 w = wr[q];
            #pragma unroll
            for (int b = 0; b < BATCH; ++b) {
                const float* h = sh + b*64 + q*4;
                acc[b] += w.x*h[0] + w.y*h[1] + w.z*h[2] + w.w*h[3];
            }
        }
        const float bias = b2[c];
        #pragma unroll
        for (int b = 0; b < BATCH; ++b)
            g_bias[b*N_LAYERS*CH + idx] = acc[b] + bias;
    }
}

// =========================================================================
// FUSED 4-layer LVC conv with 3-buffer half-weight cp.async pipeline.
// Smem: 3 x 48KB W half-buffers + xbf (bf16x2 activations). No yf32:
// pack + residual regs read x directly from gmem (DRAM idle, 2nd read L2-hot).
// Per half-phase: wait_group 1; sync; issue cp(half j+2); MMA(half j).
// =========================================================================
#define SMEM_FUSED ((3*WHW + 64*XBW) * 4)   /* 194560 B */

__global__ void __launch_bounds__(512, 1)
lvc_fused(const float* __restrict__ x, float* __restrict__ out,
          const float* __restrict__ alpha) {
    extern __shared__ __align__(16) uint32_t smem[];
    uint32_t* xbf = smem + 3*WHW;               // 64 x XBW

    const int tid  = threadIdx.x;
    const int wid  = tid >> 5;
    const int lane = tid & 31;
    const int wr   = wid & 3;                   // co group (32)
    const int wc   = wid >> 2;                  // t group (40)

    uint32_t dWb[3];
    dWb[0] = smem_u32(smem);
    dWb[1] = dWb[0] + WHW*4;
    dWb[2] = dWb[0] + 2*WHW*4;

    // prologue: prefetch layer-0 halves 0,1 of first work item
    {
        const int b0 = blockIdx.x >> 7;
        const uint32_t* Wg = g_Wh + (size_t)(b0*N_LAYERS)*WFULL;
        #pragma unroll
        for (int i = tid; i < WHW/4; i += 512) cp16(dWb[0] + i*16, Wg + i*4);
        CP_COMMIT();
        #pragma unroll
        for (int i = tid; i < WHW/4; i += 512) cp16(dWb[1] + i*16, Wg + WHW + i*4);
        CP_COMMIT();
    }
    int buf = 0;

    for (int g = blockIdx.x; g < BATCH*TILES; g += NCTAS) {
        const int b    = g >> 7;
        const int tile = g & (TILES - 1);
        const int t0   = tile * NT;
        const float* xb = x   + (size_t)b*CH*T_AUDIO;
        float*       ob = out + (size_t)b*CH*T_AUDIO;

        // ---- pack x -> xbf (direct LDG; overlaps in-flight W cps) ----
        #pragma unroll
        for (int i = tid; i < 64*BUFW; i += 512) {
            const int pr = i / BUFW;
            const int tl = i - pr*BUFW;
            const int t  = t0 - 16 + tl;
            float lo = 0.0f, hi = 0.0f;
            if (t >= 0 && t < T_AUDIO) {
                lo = xb[(size_t)(2*pr)*T_AUDIO + t];
                hi = xb[(size_t)(2*pr + 1)*T_AUDIO + t];
            }
            xbf[pr*XBW + 8 + tl] = pack_bf16x2(lo, hi);
        }
        // ---- residual regs from gmem (same region: L2-hot) ----
        float res[2][5][4];
        #pragma unroll
        for (int mt = 0; mt < 2; ++mt) {
            #pragma unroll
            for (int n = 0; n < 5; ++n) {
                const int c0 = wc*40 + n*8 + (lane & 3)*2;
                const int t  = t0 - 16 + c0;
                #pragma unroll
                for (int h = 0; h < 2; ++h) {
                    const int cog = wr*32 + mt*16 + (lane >> 2) + h*8;
                    if (t >= 0 && t + 1 < T_AUDIO) {
                        const float2 xv = *(const float2*)&xb[(size_t)cog*T_AUDIO + t];
                        res[mt][n][h*2+0] = xv.x;
                        res[mt][n][h*2+1] = xv.y;
                    } else {
                        res[mt][n][h*2+0] = (t >= 0 && t < T_AUDIO)
                                            ? xb[(size_t)cog*T_AUDIO + t] : 0.0f;
                        res[mt][n][h*2+1] = (t+1 >= 0 && t+1 < T_AUDIO)
                                            ? xb[(size_t)cog*T_AUDIO + t + 1] : 0.0f;
                    }
                }
            }
        }

        // ---- 4 layers, 2 half-phases each ----
        #pragma unroll 1
        for (int l = 0; l < N_LAYERS; ++l) {
            const int dil = 1 << l;

            float bias_l[2][2];
            #pragma unroll
            for (int mt = 0; mt < 2; ++mt)
                #pragma unroll
                for (int h = 0; h < 2; ++h)
                    bias_l[mt][h] = g_bias[(b*N_LAYERS + l)*CH
                                           + wr*32 + mt*16 + (lane >> 2) + h*8];

            float acc[2][5][4];
            #pragma unroll
            for (int mt = 0; mt < 2; ++mt)
                #pragma unroll
                for (int n = 0; n < 5; ++n)
                    #pragma unroll
                    for (int q = 0; q < 4; ++q) acc[mt][n][q] = 0.0f;

            #pragma unroll 1
            for (int h = 0; h < 2; ++h) {
                CP_WAIT1();
                __syncthreads();   // half (l,h) ready everywhere; prev MMA done

                // issue cp for half j+2 = (l+1, h) (or next tile's layer 0)
                {
                    int tgt = buf + 2; if (tgt >= 3) tgt -= 3;
                    const uint32_t* src = nullptr;
                    if (l < 3) {
                        src = g_Wh + (size_t)(b*N_LAYERS + l + 1)*WFULL + h*WHW;
                    } else {
                        const int gn = g + NCTAS;
                        if (gn < BATCH*TILES)
                            src = g_Wh + (size_t)((gn >> 7)*N_LAYERS)*WFULL + h*WHW;
                    }
                    if (src) {
                        #pragma unroll
                        for (int i = tid; i < WHW/4; i += 512)
                            cp16(dWb[tgt] + i*16, src + i*4);
                    }
                    CP_COMMIT();   // empty group when src==nullptr keeps counts uniform
                }

                // MMA over the 12 ks of this half
                const uint32_t* sWb = smem + buf*WHW;
                #pragma unroll
                for (int ksl = 0; ksl < 12; ++ksl) {
                    const int ks   = h*12 + ksl;
                    const int kk   = ks >> 3;
                    const int off  = 8 + (kk - 1)*dil;
                    const int row0 = (ks & 7)*8 + (lane & 3);
                    const uint32_t* xrow = xbf + row0*XBW + wc*40 + (lane >> 2) + off;
                    uint32_t a[2][4];
                    #pragma unroll
                    for (int mt = 0; mt < 2; ++mt) {
                        const uint4 av = *(const uint4*)(sWb + ((ksl*8 + wr*2 + mt)*32 + lane)*4);
                        a[mt][0] = av.x; a[mt][1] = av.y; a[mt][2] = av.z; a[mt][3] = av.w;
                    }
                    #pragma unroll
                    for (int n = 0; n < 5; ++n) {
                        uint32_t bf[2];
                        bf[0] = xrow[n*8];
                        bf[1] = xrow[n*8 + 4*XBW];
                        MMA16(acc[0][n], a[0], bf);
                        MMA16(acc[1][n], a[1], bf);
                    }
                }
                buf = buf + 1; if (buf >= 3) buf -= 3;
            }
            __syncthreads();   // all warps done reading xbf for this layer

            // ---- epilogue: residual in regs; repack xbf or final out ----
            if (l < 3) {
                #pragma unroll
                for (int mt = 0; mt < 2; ++mt) {
                    #pragma unroll
                    for (int n = 0; n < 5; ++n) {
                        const int c0 = wc*40 + n*8 + (lane & 3)*2;
                        #pragma unroll
                        for (int h = 0; h < 2; ++h) {
                            const int cog = wr*32 + mt*16 + (lane >> 2) + h*8;
                            const float y0 = acc[mt][n][h*2+0] + bias_l[mt][h] + res[mt][n][h*2+0];
                            const float y1 = acc[mt][n][h*2+1] + bias_l[mt][h] + res[mt][n][h*2+1];
                            res[mt][n][h*2+0] = y0;
                            res[mt][n][h*2+1] = y1;
                            const float o0 = __shfl_xor_sync(0xffffffffu, y0, 4);
                            const float o1 = __shfl_xor_sync(0xffffffffu, y1, 4);
                            if ((lane & 4) == 0) {
                                uint2 w;
                                w.x = pack_bf16x2(y0, o0);
                                w.y = pack_bf16x2(y1, o1);
                                *(uint2*)&xbf[(cog >> 1)*XBW + 8 + c0] = w;
                            }
                        }
                    }
                }
            } else {
                float al[2][2];
                #pragma unroll
                for (int mt = 0; mt < 2; ++mt)
                    #pragma unroll
                    for (int h = 0; h < 2; ++h)
                        al[mt][h] = alpha[wr*32 + mt*16 + (lane >> 2) + h*8];
                #pragma unroll
                for (int mt = 0; mt < 2; ++mt) {
                    #pragma unroll
                    for (int n = 0; n < 5; ++n) {
                        const int c0 = wc*40 + n*8 + (lane & 3)*2;
                        if (c0 >= 16 && c0 < 144) {
                            #pragma unroll
                            for (int h = 0; h < 2; ++h) {
                                const int cog = wr*32 + mt*16 + (lane >> 2) + h*8;
                                const float y0 = acc[mt][n][h*2+0] + bias_l[mt][h] + res[mt][n][h*2+0];
                                const float y1 = acc[mt][n][h*2+1] + bias_l[mt][h] + res[mt][n][h*2+1];
                                const float a = al[mt][h];
                                const float inva = 1.0f/(a + 1e-8f);
                                const float s0 = sinf(a*y0), s1 = sinf(a*y1);
                                float2 v;
                                v.x = y0 + inva*s0*s0;
                                v.y = y1 + inva*s1*s1;
                                *(float2*)&ob[(size_t)cog*T_AUDIO + t0 + (c0 - 16)] = v;
                            }
                        }
                    }
                }
            }
        }
    }
}

// =========================================================================
extern "C" void kernel_launch(void* const* d_in, const int* in_sizes, int n_in,
                              void* d_out, int out_size) {
    const float* x     = (const float*)d_in[0];
    const float* cond  = (const float*)d_in[1];
    const float* w0    = (const float*)d_in[2];
    const float* b0    = (const float*)d_in[3];
    const float* w1    = (const float*)d_in[4];
    const float* b1    = (const float*)d_in[5];
    const float* w2    = (const float*)d_in[6];
    const float* b2    = (const float*)d_in[7];
    const float* alpha = (const float*)d_in[8];
    float* out = (float*)d_out;

    cond_l0_kernel<<<dim3(8, BATCH), 256>>>(cond, w0, b0);

    const int smemC2 = (64*34 + 64*192) * (int)sizeof(float);
    cudaFuncSetAttribute(cond_l1_kernel, cudaFuncAttributeMaxDynamicSharedMemorySize, smemC2);
    cond_l1_kernel<<<BATCH, 1024, smemC2>>>(w1, b1);

    weights_kernel<<<386, 256>>>(w2, b2);

    cudaFuncSetAttribute(lvc_fused, cudaFuncAttributeMaxDynamicSharedMemorySize, SMEM_FUSED);
    lvc_fused<<<NCTAS, 512, SMEM_FUSED>>>(x, out, alpha);
}